// round 8
// baseline (speedup 1.0000x reference)
#include <cuda_runtime.h>
#include <cuda_bf16.h>
#include <mma.h>
#include <math.h>

using namespace nvcuda;

#define B_BATCH 2048
#define DMODEL  768
#define M_ROWS  (B_BATCH * 64)   // 131072

typedef __nv_bfloat16 bf16;

__device__ bf16  g_Hhi[(size_t)M_ROWS * DMODEL];
__device__ bf16  g_Hlo[(size_t)M_ROWS * DMODEL];
__device__ float g_QK [(size_t)M_ROWS * 128];
__device__ bf16  g_W1T_hi[DMODEL * DMODEL];
__device__ bf16  g_W1T_lo[DMODEL * DMODEL];
__device__ bf16  g_WqkT_hi[128 * DMODEL];
__device__ bf16  g_WqkT_lo[128 * DMODEL];

// ---------------- helpers ----------------
__device__ __forceinline__ unsigned s2u(const void* p) {
    unsigned a;
    asm("{ .reg .u64 t; cvta.to.shared.u64 t, %1; cvt.u32.u64 %0, t; }" : "=r"(a) : "l"(p));
    return a;
}
__device__ __forceinline__ void cp16(unsigned dst, const void* src) {
    asm volatile("cp.async.cg.shared.global [%0], [%1], 16;" :: "r"(dst), "l"(src));
}
#define CP_COMMIT() asm volatile("cp.async.commit_group;" ::: "memory")
#define CP_WAIT0()  asm volatile("cp.async.wait_group 0;" ::: "memory")

__device__ __forceinline__ unsigned bf2u(__nv_bfloat162 v) { return *reinterpret_cast<unsigned*>(&v); }

// mish(x) = x*tanh(softplus(x)) = x*(t^2+2t)/(t^2+2t+2), t=e^x
__device__ __forceinline__ float mish_f(float x) {
    if (x > 40.0f) return x;
    float t = __expf(x);
    float u = t * t + 2.0f * t;
    return x * (u / (u + 2.0f));
}

// ---- geometry: CTA tile 256(M) x 128(N), K-chunk 32, warp tile 64x64 ----
#define KC        32
#define NCHUNK    (DMODEL / KC)      // 24
#define TS        40                 // tile row stride (elements)
#define TB        80                 // tile row stride (bytes)
#define A_ROWS    256
#define B_ROWS    128
#define ASZ       (A_ROWS * TB)      // 20480
#define BSZ       (B_ROWS * TB)      // 10240
#define OFF_Ah    0
#define OFF_Al    ASZ                // 20480
#define OFF_Bh    (2 * ASZ)          // 40960
#define OFF_Bl    (2 * ASZ + BSZ)    // 51200
#define BUF_SZ    (2 * ASZ + 2 * BSZ)   // 61440
#define BUF0_OFF  512
#define SMEM_BYTES (512 + 2 * BUF_SZ)   // 123392
#define EPI_LD    132

// ---------------------------------------------------------------------------
// Weight transpose + bf16 split: src [K=768][N] fp32 -> dst [N][768] bf16.
// ---------------------------------------------------------------------------
__global__ void k_wconv(const float* __restrict__ src, int N, int mode)
{
    __shared__ float tile[32][33];
    int n0 = blockIdx.x * 32, k0 = blockIdx.y * 32;
    int tx = threadIdx.x, ty = threadIdx.y;
#pragma unroll
    for (int i = 0; i < 32; i += 8)
        tile[ty + i][tx] = src[(size_t)(k0 + ty + i) * N + n0 + tx];
    __syncthreads();
    bf16 *dhi, *dlo;
    if (mode == 0)      { dhi = g_W1T_hi;                dlo = g_W1T_lo; }
    else if (mode == 1) { dhi = g_WqkT_hi;               dlo = g_WqkT_lo; }
    else                { dhi = g_WqkT_hi + 64 * DMODEL; dlo = g_WqkT_lo + 64 * DMODEL; }
#pragma unroll
    for (int i = 0; i < 32; i += 8) {
        int n = n0 + ty + i, k = k0 + tx;
        float v = tile[tx][ty + i];
        bf16 h = __float2bfloat16(v);
        dhi[(size_t)n * DMODEL + k] = h;
        dlo[(size_t)n * DMODEL + k] = __float2bfloat16(v - __bfloat162float(h));
    }
}

// ---- fragments ----
typedef wmma::fragment<wmma::matrix_a, 16, 16, 16, bf16, wmma::row_major> FragA;
typedef wmma::fragment<wmma::matrix_b, 16, 16, 16, bf16, wmma::col_major> FragB;
typedef wmma::fragment<wmma::accumulator, 16, 16, 16, float> FragC;

// 64x64 warp tile, 3-term split, i-interleaved for ILP
__device__ __forceinline__ void compute_chunk(const char* buf, int wm, int wn,
                                              FragC c[4][4])
{
    const bf16* Ah = (const bf16*)(buf + OFF_Ah);
    const bf16* Al = (const bf16*)(buf + OFF_Al);
    const bf16* Bh = (const bf16*)(buf + OFF_Bh);
    const bf16* Bl = (const bf16*)(buf + OFF_Bl);
#pragma unroll
    for (int ks = 0; ks < 2; ks++) {
        FragA ah[4], al[4];
#pragma unroll
        for (int i = 0; i < 4; i++) {
            wmma::load_matrix_sync(ah[i], Ah + (wm * 64 + i * 16) * TS + ks * 16, TS);
            wmma::load_matrix_sync(al[i], Al + (wm * 64 + i * 16) * TS + ks * 16, TS);
        }
#pragma unroll
        for (int j = 0; j < 4; j++) {
            FragB bh, bl;
            wmma::load_matrix_sync(bh, Bh + (wn * 64 + j * 16) * TS + ks * 16, TS);
            wmma::load_matrix_sync(bl, Bl + (wn * 64 + j * 16) * TS + ks * 16, TS);
            wmma::mma_sync(c[0][j], ah[0], bh, c[0][j]);
            wmma::mma_sync(c[1][j], ah[1], bh, c[1][j]);
            wmma::mma_sync(c[2][j], ah[2], bh, c[2][j]);
            wmma::mma_sync(c[3][j], ah[3], bh, c[3][j]);
            wmma::mma_sync(c[0][j], ah[0], bl, c[0][j]);
            wmma::mma_sync(c[1][j], ah[1], bl, c[1][j]);
            wmma::mma_sync(c[2][j], ah[2], bl, c[2][j]);
            wmma::mma_sync(c[3][j], ah[3], bl, c[3][j]);
            wmma::mma_sync(c[0][j], al[0], bh, c[0][j]);
            wmma::mma_sync(c[1][j], al[1], bh, c[1][j]);
            wmma::mma_sync(c[2][j], al[2], bh, c[2][j]);
            wmma::mma_sync(c[3][j], al[3], bh, c[3][j]);
        }
    }
}

// stage one 128-row hi/lo pair (W tiles): r = tid>>1, half = tid&1, 32B each
__device__ __forceinline__ void stage_W(unsigned bufu,
                                        const bf16* __restrict__ whi,
                                        const bf16* __restrict__ wlo,
                                        int r, int half)
{
    unsigned dh = bufu + OFF_Bh + r * TB + half * 32;
    unsigned dl = bufu + OFF_Bl + r * TB + half * 32;
    const bf16* sh = whi + half * 16;
    const bf16* sl = wlo + half * 16;
    cp16(dh, sh); cp16(dh + 16, sh + 8);
    cp16(dl, sl); cp16(dl + 16, sl + 8);
}
// stage one 256-row hi/lo A pair from bf16 global (kernel B): row = tid, 64B each
__device__ __forceinline__ void stage_Abf(unsigned bufu,
                                          const bf16* __restrict__ ahi,
                                          const bf16* __restrict__ alo, int row)
{
    unsigned dh = bufu + OFF_Ah + row * TB;
    unsigned dl = bufu + OFF_Al + row * TB;
#pragma unroll
    for (int j = 0; j < 4; j++) {
        cp16(dh + j * 16, ahi + j * 8);
        cp16(dl + j * 16, alo + j * 8);
    }
}
// convert 32 fp32 (in regs) -> hi/lo bf16 rows (64B each), row = tid
__device__ __forceinline__ void convert_store_x(char* buf, int row, const float4 v[8])
{
    char* dh = buf + OFF_Ah + row * TB;
    char* dl = buf + OFF_Al + row * TB;
#pragma unroll
    for (int p = 0; p < 4; p++) {
        float4 a = v[2 * p], b = v[2 * p + 1];
        __nv_bfloat162 h0 = __floats2bfloat162_rn(a.x, a.y);
        __nv_bfloat162 h1 = __floats2bfloat162_rn(a.z, a.w);
        __nv_bfloat162 h2 = __floats2bfloat162_rn(b.x, b.y);
        __nv_bfloat162 h3 = __floats2bfloat162_rn(b.z, b.w);
        __nv_bfloat162 l0 = __floats2bfloat162_rn(a.x - __bfloat162float(h0.x), a.y - __bfloat162float(h0.y));
        __nv_bfloat162 l1 = __floats2bfloat162_rn(a.z - __bfloat162float(h1.x), a.w - __bfloat162float(h1.y));
        __nv_bfloat162 l2 = __floats2bfloat162_rn(b.x - __bfloat162float(h2.x), b.y - __bfloat162float(h2.y));
        __nv_bfloat162 l3 = __floats2bfloat162_rn(b.z - __bfloat162float(h3.x), b.w - __bfloat162float(h3.y));
        *(uint4*)(dh + p * 16) = make_uint4(bf2u(h0), bf2u(h1), bf2u(h2), bf2u(h3));
        *(uint4*)(dl + p * 16) = make_uint4(bf2u(l0), bf2u(l1), bf2u(l2), bf2u(l3));
    }
}

// ---------------------------------------------------------------------------
// Kernel A: H = mish(X @ W1 + b1) -> g_Hhi/g_Hlo.
// grid (6, 512), 256 thr, CTA tile 256x128.
// ---------------------------------------------------------------------------
__global__ __launch_bounds__(256, 1) void k_gemmA(const float* __restrict__ X,
                                                  const float* __restrict__ b1)
{
    extern __shared__ char smem[];
    const unsigned sb = s2u(smem);
    float* bias = (float*)smem;
    const int tid = threadIdx.x, wid = tid >> 5;
    const int wm = wid >> 1, wn = wid & 1;
    const int n0 = blockIdx.x * 128, m0 = blockIdx.y * 256;
    const int r = tid >> 1, half = tid & 1;

    if (tid < 128) bias[tid] = b1[n0 + tid];

    FragC c[4][4];
#pragma unroll
    for (int i = 0; i < 4; i++)
#pragma unroll
        for (int j = 0; j < 4; j++) wmma::fill_fragment(c[i][j], 0.0f);

    const float* xrow = X + (size_t)(m0 + tid) * DMODEL;            // row = tid
    const bf16*  whr  = g_W1T_hi + (size_t)(n0 + r) * DMODEL;
    const bf16*  wlr  = g_W1T_lo + (size_t)(n0 + r) * DMODEL;

    // prologue: chunk 0
    {
        float4 xv[8];
        const float4* xp = (const float4*)xrow;
#pragma unroll
        for (int p = 0; p < 8; p++) xv[p] = xp[p];
        stage_W(sb + BUF0_OFF, whr, wlr, r, half);
        CP_COMMIT();
        convert_store_x(smem + BUF0_OFF, tid, xv);
        CP_WAIT0();
    }
    __syncthreads();

    for (int ch = 0; ch < NCHUNK; ch++) {
        const int cur = ch & 1;
        char* curbuf = smem + BUF0_OFF + cur * BUF_SZ;
        char* nxtbuf = smem + BUF0_OFF + (1 - cur) * BUF_SZ;
        const unsigned nxtu = sb + BUF0_OFF + (1 - cur) * BUF_SZ;

        float4 xv[8];
        if (ch < NCHUNK - 1) {
            const int k0 = (ch + 1) * KC;
            const float4* xp = (const float4*)(xrow + k0);
#pragma unroll
            for (int p = 0; p < 8; p++) xv[p] = xp[p];
            stage_W(nxtu, whr + k0, wlr + k0, r, half);
            CP_COMMIT();
        }

        compute_chunk(curbuf, wm, wn, c);

        if (ch < NCHUNK - 1) {
            convert_store_x(nxtbuf, tid, xv);
            CP_WAIT0();
        }
        __syncthreads();
    }

    // epilogue: two passes of 128 rows x 128 cols (i in {2p, 2p+1})
    float* Cs = (float*)(smem + BUF0_OFF);
#pragma unroll
    for (int p = 0; p < 2; p++) {
#pragma unroll
        for (int ii = 0; ii < 2; ii++)
#pragma unroll
            for (int j = 0; j < 4; j++)
                wmma::store_matrix_sync(Cs + (wm * 32 + ii * 16) * EPI_LD + wn * 64 + j * 16,
                                        c[2 * p + ii][j], EPI_LD, wmma::mem_row_major);
        __syncthreads();

        const int grow = m0 + ((r >> 5) * 64) + p * 32 + (r & 31);
        const float* crow = Cs + r * EPI_LD + half * 64;
        const float* bptr = bias + half * 64;
        bf16* dh = g_Hhi + (size_t)grow * DMODEL + n0 + half * 64;
        bf16* dl = g_Hlo + (size_t)grow * DMODEL + n0 + half * 64;
#pragma unroll
        for (int blk = 0; blk < 8; blk++) {
            unsigned hw[4], lw[4];
#pragma unroll
            for (int e = 0; e < 4; e++) {
                float v0 = mish_f(crow[blk * 8 + 2 * e]     + bptr[blk * 8 + 2 * e]);
                float v1 = mish_f(crow[blk * 8 + 2 * e + 1] + bptr[blk * 8 + 2 * e + 1]);
                __nv_bfloat162 hh = __floats2bfloat162_rn(v0, v1);
                __nv_bfloat162 ll = __floats2bfloat162_rn(v0 - __bfloat162float(hh.x),
                                                          v1 - __bfloat162float(hh.y));
                hw[e] = bf2u(hh); lw[e] = bf2u(ll);
            }
            *(uint4*)(dh + blk * 8) = make_uint4(hw[0], hw[1], hw[2], hw[3]);
            *(uint4*)(dl + blk * 8) = make_uint4(lw[0], lw[1], lw[2], lw[3]);
        }
        __syncthreads();
    }
}

// ---------------------------------------------------------------------------
// Kernel B: QK = H @ [Wq|Wk] + bias -> g_QK fp32. grid 512, CTA tile 256x128.
// ---------------------------------------------------------------------------
__global__ __launch_bounds__(256, 1) void k_gemmB(const float* __restrict__ bq,
                                                  const float* __restrict__ bk)
{
    extern __shared__ char smem[];
    const unsigned sb = s2u(smem);
    float* bias = (float*)smem;
    const int tid = threadIdx.x, wid = tid >> 5;
    const int wm = wid >> 1, wn = wid & 1;
    const int m0 = blockIdx.x * 256;
    const int r = tid >> 1, half = tid & 1;

    if (tid < 128) bias[tid] = (tid < 64) ? bq[tid] : bk[tid - 64];

    FragC c[4][4];
#pragma unroll
    for (int i = 0; i < 4; i++)
#pragma unroll
        for (int j = 0; j < 4; j++) wmma::fill_fragment(c[i][j], 0.0f);

    const bf16* ahr = g_Hhi + (size_t)(m0 + tid) * DMODEL;
    const bf16* alr = g_Hlo + (size_t)(m0 + tid) * DMODEL;
    const bf16* whr = g_WqkT_hi + (size_t)r * DMODEL;
    const bf16* wlr = g_WqkT_lo + (size_t)r * DMODEL;

    stage_Abf(sb + BUF0_OFF, ahr, alr, tid);
    stage_W(sb + BUF0_OFF, whr, wlr, r, half);
    CP_COMMIT();
    CP_WAIT0();
    __syncthreads();

    for (int ch = 0; ch < NCHUNK; ch++) {
        const int cur = ch & 1;
        char* curbuf = smem + BUF0_OFF + cur * BUF_SZ;
        const unsigned nxtu = sb + BUF0_OFF + (1 - cur) * BUF_SZ;

        if (ch < NCHUNK - 1) {
            const int k0 = (ch + 1) * KC;
            stage_Abf(nxtu, ahr + k0, alr + k0, tid);
            stage_W(nxtu, whr + k0, wlr + k0, r, half);
            CP_COMMIT();
        }
        compute_chunk(curbuf, wm, wn, c);
        if (ch < NCHUNK - 1) CP_WAIT0();
        __syncthreads();
    }

    float* Cs = (float*)(smem + BUF0_OFF);
#pragma unroll
    for (int p = 0; p < 2; p++) {
#pragma unroll
        for (int ii = 0; ii < 2; ii++)
#pragma unroll
            for (int j = 0; j < 4; j++)
                wmma::store_matrix_sync(Cs + (wm * 32 + ii * 16) * EPI_LD + wn * 64 + j * 16,
                                        c[2 * p + ii][j], EPI_LD, wmma::mem_row_major);
        __syncthreads();

        const int grow = m0 + ((r >> 5) * 64) + p * 32 + (r & 31);
        const float* crow = Cs + r * EPI_LD + half * 64;
        const float* bptr = bias + half * 64;
        float* orow = g_QK + (size_t)grow * 128 + half * 64;
#pragma unroll
        for (int blk = 0; blk < 16; blk++) {
            float4 o;
            o.x = crow[blk * 4 + 0] + bptr[blk * 4 + 0];
            o.y = crow[blk * 4 + 1] + bptr[blk * 4 + 1];
            o.z = crow[blk * 4 + 2] + bptr[blk * 4 + 2];
            o.w = crow[blk * 4 + 3] + bptr[blk * 4 + 3];
            *(float4*)(orow + blk * 4) = o;
        }
        __syncthreads();
    }
}

// ---------------------------------------------------------------------------
// Kernel C: per-batch scores (4x4 register tiles) + promotion + gather.
// ---------------------------------------------------------------------------
__global__ __launch_bounds__(256) void k_scores_gather(
    const float* __restrict__ Wp, const float* __restrict__ bp,
    const int* __restrict__ indices, float* __restrict__ out)
{
    __shared__ float q_s[64][65];
    __shared__ float k_s[64][65];
    __shared__ float s_s[64][64];
    __shared__ float prom2[24];

    const int b = blockIdx.x, tid = threadIdx.x;
    for (int i = tid; i < 64 * 64; i += 256) {
        int rr = i >> 6, cc = i & 63;
        const float* row = &g_QK[((size_t)b * 64 + rr) * 128];
        q_s[rr][cc] = row[cc];
        k_s[rr][cc] = row[64 + cc];
    }
    __syncthreads();

    {
        const int tx = tid & 15, ty = tid >> 4;
        const int i0 = ty * 4, j0 = tx * 4;
        float acc[4][4] = {};
#pragma unroll 16
        for (int d = 0; d < 64; d++) {
            float qv[4], kv[4];
#pragma unroll
            for (int a = 0; a < 4; a++) { qv[a] = q_s[i0 + a][d]; kv[a] = k_s[j0 + a][d]; }
#pragma unroll
            for (int a = 0; a < 4; a++)
#pragma unroll
                for (int e = 0; e < 4; e++) acc[a][e] += qv[a] * kv[e];
        }
#pragma unroll
        for (int a = 0; a < 4; a++)
#pragma unroll
            for (int e = 0; e < 4; e++) s_s[i0 + a][j0 + e] = acc[a][e] * 0.125f;
    }

    if (tid < 24) {
        int jr = 56 + tid / 3, cc = tid % 3;
        float acc = bp[cc] + bp[3];
#pragma unroll
        for (int d = 0; d < 64; d++)
            acc += k_s[jr][d] * (Wp[d * 4 + cc] + Wp[d * 4 + 3]);
        prom2[tid] = acc;
    }
    __syncthreads();

    for (int t = tid; t < 1858; t += 256) {
        int id = indices[t];
        float v;
        if (id < 4096) v = s_s[id >> 6][id & 63];
        else {
            int p = id - 4096, i = p / 3;
            v = s_s[48 + (i >> 3)][56 + (i & 7)] + prom2[p % 24];
        }
        out[(size_t)b * 1858 + t] = v;
    }
}

// ---------------------------------------------------------------------------
extern "C" void kernel_launch(void* const* d_in, const int* in_sizes, int n_in,
                              void* d_out, int out_size)
{
    const float* x  = (const float*)d_in[0];
    const float* W1 = (const float*)d_in[1];
    const float* b1 = (const float*)d_in[2];
    const float* Wq = (const float*)d_in[3];
    const float* bq = (const float*)d_in[4];
    const float* Wk = (const float*)d_in[5];
    const float* bk = (const float*)d_in[6];
    const float* Wp = (const float*)d_in[7];
    const float* bp = (const float*)d_in[8];
    const int*  idx = (const int*)d_in[9];

    cudaFuncSetAttribute(k_gemmA, cudaFuncAttributeMaxDynamicSharedMemorySize, SMEM_BYTES);
    cudaFuncSetAttribute(k_gemmB, cudaFuncAttributeMaxDynamicSharedMemorySize, SMEM_BYTES);

    k_wconv<<<dim3(24, 24), dim3(32, 8)>>>(W1, 768, 0);
    k_wconv<<<dim3(2, 24),  dim3(32, 8)>>>(Wq, 64, 1);
    k_wconv<<<dim3(2, 24),  dim3(32, 8)>>>(Wk, 64, 2);

    k_gemmA<<<dim3(6, 512), 256, SMEM_BYTES>>>(x, b1);
    k_gemmB<<<512, 256, SMEM_BYTES>>>(bq, bk);
    k_scores_gather<<<B_BATCH, 256>>>(Wp, bp, idx, (float*)d_out);
}

// round 9
// speedup vs baseline: 2.8635x; 2.8635x over previous
#include <cuda_runtime.h>
#include <cuda_fp16.h>
#include <mma.h>
#include <math.h>

using namespace nvcuda;

#define B_BATCH 2048
#define DMODEL  768
#define M_ROWS  (B_BATCH * 64)   // 131072

__device__ __half g_Hhi[(size_t)M_ROWS * DMODEL];
__device__ __half g_Hlo[(size_t)M_ROWS * DMODEL];
__device__ float  g_QK [(size_t)M_ROWS * 128];
__device__ __half g_W1T [DMODEL * DMODEL];
__device__ __half g_WqkT[128 * DMODEL];

// ---------------- helpers ----------------
__device__ __forceinline__ unsigned s2u(const void* p) {
    unsigned a;
    asm("{ .reg .u64 t; cvta.to.shared.u64 t, %1; cvt.u32.u64 %0, t; }" : "=r"(a) : "l"(p));
    return a;
}
__device__ __forceinline__ void cp16(unsigned dst, const void* src) {
    asm volatile("cp.async.cg.shared.global [%0], [%1], 16;" :: "r"(dst), "l"(src));
}
#define CP_COMMIT() asm volatile("cp.async.commit_group;" ::: "memory")
#define CP_WAIT0()  asm volatile("cp.async.wait_group 0;" ::: "memory")

__device__ __forceinline__ unsigned h2u(__half2 v) { return *reinterpret_cast<unsigned*>(&v); }

// exact fp32 -> fp16 hi+lo split for a pair
__device__ __forceinline__ void split2(float x, float y, unsigned& hi, unsigned& lo) {
    __half2 h = __floats2half2_rn(x, y);
    __half2 l = __floats2half2_rn(x - __low2float(h), y - __high2float(h));
    hi = h2u(h); lo = h2u(l);
}

// mish(x) = x*tanh(softplus(x)) = x*(t^2+2t)/(t^2+2t+2), t=e^x
__device__ __forceinline__ float mish_f(float x) {
    if (x > 40.0f) return x;
    float t = __expf(x);
    float u = t * t + 2.0f * t;
    return x * (u / (u + 2.0f));
}

// ---- geometry (R5-proven): CTA 128x128, K-chunk 32, warp tile 32x64 ----
#define KC        32
#define NCHUNK    (DMODEL / KC)      // 24
#define TS        40                 // tile row stride (elements)
#define TB        80                 // tile row stride (bytes)
#define TILE_SZ   10240              // 128 rows x 80B
#define OFF_Ah    0
#define OFF_Al    TILE_SZ
#define OFF_B     (2 * TILE_SZ)
#define BUF_SZ    (3 * TILE_SZ)      // 30720
#define BUF0_OFF  512
#define EPI_LD    132
#define SMEM_BYTES (512 + 128 * EPI_LD * 4)   // 68096 (> 512 + 2*BUF_SZ = 61952)

// ---------------------------------------------------------------------------
// Weight transpose to fp16: src [K=768][N] fp32 -> dst [N][768] fp16.
// ---------------------------------------------------------------------------
__global__ void k_wconv(const float* __restrict__ src, int N, int mode)
{
    __shared__ float tile[32][33];
    int n0 = blockIdx.x * 32, k0 = blockIdx.y * 32;
    int tx = threadIdx.x, ty = threadIdx.y;
#pragma unroll
    for (int i = 0; i < 32; i += 8)
        tile[ty + i][tx] = src[(size_t)(k0 + ty + i) * N + n0 + tx];
    __syncthreads();
    __half* dst;
    if (mode == 0)      dst = g_W1T;
    else if (mode == 1) dst = g_WqkT;
    else                dst = g_WqkT + 64 * DMODEL;
#pragma unroll
    for (int i = 0; i < 32; i += 8) {
        int n = n0 + ty + i, k = k0 + tx;
        dst[(size_t)n * DMODEL + k] = __float2half_rn(tile[tx][ty + i]);
    }
}

// ---- fragments ----
typedef wmma::fragment<wmma::matrix_a, 16, 16, 16, __half, wmma::row_major> FragA;
typedef wmma::fragment<wmma::matrix_b, 16, 16, 16, __half, wmma::col_major> FragB;
typedef wmma::fragment<wmma::accumulator, 16, 16, 16, float> FragC;

// 32x64 warp tile, 2-term split (A exact, B single)
__device__ __forceinline__ void compute_chunk(const char* buf, int wm, int wn,
                                              FragC c[2][4])
{
    const __half* Ah = (const __half*)(buf + OFF_Ah);
    const __half* Al = (const __half*)(buf + OFF_Al);
    const __half* Bs = (const __half*)(buf + OFF_B);
#pragma unroll
    for (int ks = 0; ks < 2; ks++) {
        FragA ah[2], al[2];
#pragma unroll
        for (int i = 0; i < 2; i++) {
            wmma::load_matrix_sync(ah[i], Ah + (wm * 32 + i * 16) * TS + ks * 16, TS);
            wmma::load_matrix_sync(al[i], Al + (wm * 32 + i * 16) * TS + ks * 16, TS);
        }
#pragma unroll
        for (int j = 0; j < 4; j++) {
            FragB b;
            wmma::load_matrix_sync(b, Bs + (wn * 64 + j * 16) * TS + ks * 16, TS);
            wmma::mma_sync(c[0][j], ah[0], b, c[0][j]);
            wmma::mma_sync(c[1][j], ah[1], b, c[1][j]);
            wmma::mma_sync(c[0][j], al[0], b, c[0][j]);
            wmma::mma_sync(c[1][j], al[1], b, c[1][j]);
        }
    }
}

// stage 16 fp16 (32B) of one row via cp.async
__device__ __forceinline__ void stage_row32(unsigned dst, const __half* __restrict__ s)
{
    cp16(dst, s);
    cp16(dst + 16, s + 8);
}

// convert 16 fp32 (in regs) -> fp16 hi/lo, store 32B each
__device__ __forceinline__ void convert_store_x(char* dst_hi, char* dst_lo,
                                                const float4 v[4])
{
#pragma unroll
    for (int p = 0; p < 2; p++) {
        float4 a = v[2 * p], b = v[2 * p + 1];
        unsigned h0, l0, h1, l1, h2, l2, h3, l3;
        split2(a.x, a.y, h0, l0);
        split2(a.z, a.w, h1, l1);
        split2(b.x, b.y, h2, l2);
        split2(b.z, b.w, h3, l3);
        *(uint4*)(dst_hi + p * 16) = make_uint4(h0, h1, h2, h3);
        *(uint4*)(dst_lo + p * 16) = make_uint4(l0, l1, l2, l3);
    }
}

// ---------------------------------------------------------------------------
// Kernel A: H = mish(X @ W1 + b1) -> g_Hhi/g_Hlo. grid (6,1024), 256 thr.
// ---------------------------------------------------------------------------
__global__ __launch_bounds__(256, 2) void k_gemmA(const float* __restrict__ X,
                                                  const float* __restrict__ b1)
{
    extern __shared__ char smem[];
    const unsigned sb = s2u(smem);
    float* bias = (float*)smem;
    const int tid = threadIdx.x, wid = tid >> 5;
    const int wm = wid & 3, wn = wid >> 2;
    const int n0 = blockIdx.x * 128, m0 = blockIdx.y * 128;
    const int r = tid >> 1, half = tid & 1;

    if (tid < 128) bias[tid] = b1[n0 + tid];

    FragC c[2][4];
#pragma unroll
    for (int i = 0; i < 2; i++)
#pragma unroll
        for (int j = 0; j < 4; j++) wmma::fill_fragment(c[i][j], 0.0f);

    const float*  xrow = X + (size_t)(m0 + r) * DMODEL + half * 16;
    const __half* wr   = g_W1T + (size_t)(n0 + r) * DMODEL + half * 16;
    const unsigned arow = r * TB + half * 32;

    // prologue: chunk 0
    {
        float4 xv[4];
        const float4* xp = (const float4*)xrow;
#pragma unroll
        for (int p = 0; p < 4; p++) xv[p] = xp[p];
        stage_row32(sb + BUF0_OFF + OFF_B + arow, wr);
        CP_COMMIT();
        convert_store_x(smem + BUF0_OFF + OFF_Ah + arow,
                        smem + BUF0_OFF + OFF_Al + arow, xv);
        CP_WAIT0();
    }
    __syncthreads();

    for (int ch = 0; ch < NCHUNK; ch++) {
        const int cur = ch & 1;
        char* curbuf = smem + BUF0_OFF + cur * BUF_SZ;
        char* nxtbuf = smem + BUF0_OFF + (1 - cur) * BUF_SZ;
        const unsigned nxtu = sb + BUF0_OFF + (1 - cur) * BUF_SZ;

        float4 xv[4];
        if (ch < NCHUNK - 1) {
            const int k0 = (ch + 1) * KC;
            const float4* xp = (const float4*)(xrow + k0);
#pragma unroll
            for (int p = 0; p < 4; p++) xv[p] = xp[p];
            stage_row32(nxtu + OFF_B + arow, wr + k0);
            CP_COMMIT();
        }

        compute_chunk(curbuf, wm, wn, c);

        if (ch < NCHUNK - 1) {
            convert_store_x(nxtbuf + OFF_Ah + arow, nxtbuf + OFF_Al + arow, xv);
            CP_WAIT0();
        }
        __syncthreads();
    }

    // epilogue: dump accumulators, bias + mish + split, store
    float* Cs = (float*)(smem + BUF0_OFF);
#pragma unroll
    for (int i = 0; i < 2; i++)
#pragma unroll
        for (int j = 0; j < 4; j++)
            wmma::store_matrix_sync(Cs + (wm * 32 + i * 16) * EPI_LD + wn * 64 + j * 16,
                                    c[i][j], EPI_LD, wmma::mem_row_major);
    __syncthreads();

    const float* crow = Cs + r * EPI_LD + half * 64;
    const float* bptr = bias + half * 64;
    __half* dh = g_Hhi + (size_t)(m0 + r) * DMODEL + n0 + half * 64;
    __half* dl = g_Hlo + (size_t)(m0 + r) * DMODEL + n0 + half * 64;
#pragma unroll
    for (int blk = 0; blk < 8; blk++) {
        unsigned hw[4], lw[4];
#pragma unroll
        for (int e = 0; e < 4; e++) {
            float v0 = mish_f(crow[blk * 8 + 2 * e]     + bptr[blk * 8 + 2 * e]);
            float v1 = mish_f(crow[blk * 8 + 2 * e + 1] + bptr[blk * 8 + 2 * e + 1]);
            split2(v0, v1, hw[e], lw[e]);
        }
        *(uint4*)(dh + blk * 8) = make_uint4(hw[0], hw[1], hw[2], hw[3]);
        *(uint4*)(dl + blk * 8) = make_uint4(lw[0], lw[1], lw[2], lw[3]);
    }
}

// ---------------------------------------------------------------------------
// Kernel B: QK = H @ [Wq|Wk] + bias -> g_QK fp32.  grid 1024, 256 thr.
// ---------------------------------------------------------------------------
__global__ __launch_bounds__(256, 2) void k_gemmB(const float* __restrict__ bq,
                                                  const float* __restrict__ bk)
{
    extern __shared__ char smem[];
    const unsigned sb = s2u(smem);
    float* bias = (float*)smem;
    const int tid = threadIdx.x, wid = tid >> 5;
    const int wm = wid & 3, wn = wid >> 2;
    const int m0 = blockIdx.x * 128;
    const int r = tid >> 1, half = tid & 1;

    if (tid < 128) bias[tid] = (tid < 64) ? bq[tid] : bk[tid - 64];

    FragC c[2][4];
#pragma unroll
    for (int i = 0; i < 2; i++)
#pragma unroll
        for (int j = 0; j < 4; j++) wmma::fill_fragment(c[i][j], 0.0f);

    const __half* ahr = g_Hhi + (size_t)(m0 + r) * DMODEL + half * 16;
    const __half* alr = g_Hlo + (size_t)(m0 + r) * DMODEL + half * 16;
    const __half* wr  = g_WqkT + (size_t)r * DMODEL + half * 16;
    const unsigned arow = r * TB + half * 32;

    stage_row32(sb + BUF0_OFF + OFF_Ah + arow, ahr);
    stage_row32(sb + BUF0_OFF + OFF_Al + arow, alr);
    stage_row32(sb + BUF0_OFF + OFF_B  + arow, wr);
    CP_COMMIT();
    CP_WAIT0();
    __syncthreads();

    for (int ch = 0; ch < NCHUNK; ch++) {
        const int cur = ch & 1;
        char* curbuf = smem + BUF0_OFF + cur * BUF_SZ;
        const unsigned nxtu = sb + BUF0_OFF + (1 - cur) * BUF_SZ;

        if (ch < NCHUNK - 1) {
            const int k0 = (ch + 1) * KC;
            stage_row32(nxtu + OFF_Ah + arow, ahr + k0);
            stage_row32(nxtu + OFF_Al + arow, alr + k0);
            stage_row32(nxtu + OFF_B  + arow, wr + k0);
            CP_COMMIT();
        }
        compute_chunk(curbuf, wm, wn, c);
        if (ch < NCHUNK - 1) CP_WAIT0();
        __syncthreads();
    }

    float* Cs = (float*)(smem + BUF0_OFF);
#pragma unroll
    for (int i = 0; i < 2; i++)
#pragma unroll
        for (int j = 0; j < 4; j++)
            wmma::store_matrix_sync(Cs + (wm * 32 + i * 16) * EPI_LD + wn * 64 + j * 16,
                                    c[i][j], EPI_LD, wmma::mem_row_major);
    __syncthreads();

    const float* crow = Cs + r * EPI_LD + half * 64;
    const float* bptr = bias + half * 64;
    float* orow = g_QK + (size_t)(m0 + r) * 128 + half * 64;
#pragma unroll
    for (int blk = 0; blk < 16; blk++) {
        float4 o;
        o.x = crow[blk * 4 + 0] + bptr[blk * 4 + 0];
        o.y = crow[blk * 4 + 1] + bptr[blk * 4 + 1];
        o.z = crow[blk * 4 + 2] + bptr[blk * 4 + 2];
        o.w = crow[blk * 4 + 3] + bptr[blk * 4 + 3];
        *(float4*)(orow + blk * 4) = o;
    }
}

// ---------------------------------------------------------------------------
// Kernel C: per-batch scores (4x4 register tiles) + promotion + gather.
// ---------------------------------------------------------------------------
__global__ __launch_bounds__(256) void k_scores_gather(
    const float* __restrict__ Wp, const float* __restrict__ bp,
    const int* __restrict__ indices, float* __restrict__ out)
{
    __shared__ float q_s[64][65];
    __shared__ float k_s[64][65];
    __shared__ float s_s[64][64];
    __shared__ float prom2[24];

    const int b = blockIdx.x, tid = threadIdx.x;
    for (int i = tid; i < 64 * 64; i += 256) {
        int rr = i >> 6, cc = i & 63;
        const float* row = &g_QK[((size_t)b * 64 + rr) * 128];
        q_s[rr][cc] = row[cc];
        k_s[rr][cc] = row[64 + cc];
    }
    __syncthreads();

    {
        const int tx = tid & 15, ty = tid >> 4;
        const int i0 = ty * 4, j0 = tx * 4;
        float acc[4][4] = {};
#pragma unroll 16
        for (int d = 0; d < 64; d++) {
            float qv[4], kv[4];
#pragma unroll
            for (int a = 0; a < 4; a++) { qv[a] = q_s[i0 + a][d]; kv[a] = k_s[j0 + a][d]; }
#pragma unroll
            for (int a = 0; a < 4; a++)
#pragma unroll
                for (int e = 0; e < 4; e++) acc[a][e] += qv[a] * kv[e];
        }
#pragma unroll
        for (int a = 0; a < 4; a++)
#pragma unroll
            for (int e = 0; e < 4; e++) s_s[i0 + a][j0 + e] = acc[a][e] * 0.125f;
    }

    if (tid < 24) {
        int jr = 56 + tid / 3, cc = tid % 3;
        float acc = bp[cc] + bp[3];
#pragma unroll
        for (int d = 0; d < 64; d++)
            acc += k_s[jr][d] * (Wp[d * 4 + cc] + Wp[d * 4 + 3]);
        prom2[tid] = acc;
    }
    __syncthreads();

    for (int t = tid; t < 1858; t += 256) {
        int id = indices[t];
        float v;
        if (id < 4096) v = s_s[id >> 6][id & 63];
        else {
            int p = id - 4096, i = p / 3;
            v = s_s[48 + (i >> 3)][56 + (i & 7)] + prom2[p % 24];
        }
        out[(size_t)b * 1858 + t] = v;
    }
}

// ---------------------------------------------------------------------------
extern "C" void kernel_launch(void* const* d_in, const int* in_sizes, int n_in,
                              void* d_out, int out_size)
{
    const float* x  = (const float*)d_in[0];
    const float* W1 = (const float*)d_in[1];
    const float* b1 = (const float*)d_in[2];
    const float* Wq = (const float*)d_in[3];
    const float* bq = (const float*)d_in[4];
    const float* Wk = (const float*)d_in[5];
    const float* bk = (const float*)d_in[6];
    const float* Wp = (const float*)d_in[7];
    const float* bp = (const float*)d_in[8];
    const int*  idx = (const int*)d_in[9];

    cudaFuncSetAttribute(k_gemmA, cudaFuncAttributeMaxDynamicSharedMemorySize, SMEM_BYTES);
    cudaFuncSetAttribute(k_gemmB, cudaFuncAttributeMaxDynamicSharedMemorySize, SMEM_BYTES);

    k_wconv<<<dim3(24, 24), dim3(32, 8)>>>(W1, 768, 0);
    k_wconv<<<dim3(2, 24),  dim3(32, 8)>>>(Wq, 64, 1);
    k_wconv<<<dim3(2, 24),  dim3(32, 8)>>>(Wk, 64, 2);

    k_gemmA<<<dim3(6, 1024), 256, SMEM_BYTES>>>(x, b1);
    k_gemmB<<<1024, 256, SMEM_BYTES>>>(bq, bk);
    k_scores_gather<<<B_BATCH, 256>>>(Wp, bp, idx, (float*)d_out);
}